// round 11
// baseline (speedup 1.0000x reference)
#include <cuda_runtime.h>
#include <cuda_fp16.h>
#include <math.h>

// ---------------- problem constants ----------------
#define N_USER   100000
#define N_ITEM   50000
#define NTOT     (N_USER + N_ITEM)     // 150000
#define EMB      64
#define FEAT     384
#define NNZ      2400000
#define N_PROMPT 8
#define N_LAYERS 4
#define EPS_     1e-8f

#define SCAN_BLK 256
#define NB_SCAN  ((NTOT + SCAN_BLK - 1) / SCAN_BLK)   // 586

// ---------------- device scratch (static, no runtime alloc) ----------------
__device__ float  g_ego [NTOT * EMB];     // layer-0 embeddings, fp32
__device__ __half g_hEgo[NTOT * EMB];     // half copy of ego (gather table L1)
__device__ uint2  g_q1  [NTOT * 8];       // x1 int8 rows (8 lanes x 8 bytes)
__device__ uint2  g_q2  [NTOT * 8];       // x2
__device__ uint2  g_q3  [NTOT * 8];       // x3
__device__ float  g_s1  [NTOT];           // per-row dequant scales
__device__ float  g_s2  [NTOT];
__device__ float  g_s3  [NTOT];
__device__ float  g_norm[NTOT];           // ||ego|| per row
__device__ int    g_deg   [NTOT];
__device__ int    g_rowptr[NTOT + 1];
__device__ int    g_cursor[NTOT];
__device__ int    g_bsums [1024];
__device__ int    g_boffs [1024];
__device__ int2   g_edges [NNZ];          // {col, float-bits(val)} per edge

// ---------------- 1) user ego = user_fea + prompt-sum (fused) --------------
__global__ void k_user_ego(const float* __restrict__ uf,
                           const float* __restrict__ pe) {
    int i = blockIdx.x * blockDim.x + threadIdx.x;
    if (i >= N_USER * EMB) return;
    int c = i & (EMB - 1);
    float s = 0.f;
    #pragma unroll
    for (int p = 0; p < N_PROMPT; ++p) s += __ldg(&pe[p * EMB + c]);
    float v = uf[i] + s;
    g_ego[i]  = v;
    g_hEgo[i] = __float2half(v);
}

// ---------------- 2) item GEMM + tanh -> ego (fp32 + half copy) ------------
__global__ __launch_bounds__(256) void k_gemm(const float* __restrict__ A,
                                              const float* __restrict__ B,
                                              const float* __restrict__ bias)
{
    __shared__ float As[64][32];
    __shared__ float Bs[32][64];

    const int t     = threadIdx.x;
    const int c     = t & 63;
    const int rq    = t >> 6;
    const int row0  = blockIdx.x * 64;

    float acc[16];
    #pragma unroll
    for (int j = 0; j < 16; ++j) acc[j] = 0.f;

    for (int k0 = 0; k0 < FEAT; k0 += 32) {
        #pragma unroll
        for (int i = 0; i < 8; ++i) {
            int lin = i * 256 + t;
            int r = lin >> 5, k = lin & 31;
            int gr = row0 + r;
            As[r][k] = (gr < N_ITEM) ? A[gr * FEAT + k0 + k] : 0.f;
        }
        #pragma unroll
        for (int i = 0; i < 8; ++i) {
            int lin = i * 256 + t;
            int k = lin >> 6, cc = lin & 63;
            Bs[k][cc] = B[(k0 + k) * EMB + cc];
        }
        __syncthreads();

        float bv[32];
        #pragma unroll
        for (int kk = 0; kk < 32; ++kk) bv[kk] = Bs[kk][c];

        #pragma unroll
        for (int j = 0; j < 16; ++j) {
            const float4* ar = (const float4*)&As[rq * 16 + j][0];
            #pragma unroll
            for (int q = 0; q < 8; ++q) {
                float4 a = ar[q];
                acc[j] += a.x * bv[4*q] + a.y * bv[4*q+1]
                        + a.z * bv[4*q+2] + a.w * bv[4*q+3];
            }
        }
        __syncthreads();
    }

    float bb = bias[c];
    #pragma unroll
    for (int j = 0; j < 16; ++j) {
        int row = row0 + rq * 16 + j;
        if (row < N_ITEM) {
            float v = tanhf(acc[j] + bb);
            g_ego [(N_USER + row) * EMB + c] = v;
            g_hEgo[(N_USER + row) * EMB + c] = __float2half(v);
        }
    }
}

// ---------------- CSR build (proven R8 chain) ----------------
__global__ void k_hist(const int* __restrict__ rows) {
    int e = blockIdx.x * blockDim.x + threadIdx.x;
    if (e < NNZ) atomicAdd(&g_deg[rows[e]], 1);
}
__global__ void k_scan1() {
    __shared__ int sh[SCAN_BLK];
    int t = threadIdx.x;
    int idx = blockIdx.x * SCAN_BLK + t;
    int v = (idx < NTOT) ? g_deg[idx] : 0;
    sh[t] = v;
    __syncthreads();
    for (int off = 1; off < SCAN_BLK; off <<= 1) {
        int add = (t >= off) ? sh[t - off] : 0;
        __syncthreads();
        sh[t] += add;
        __syncthreads();
    }
    if (idx < NTOT) g_rowptr[idx] = sh[t] - v;
    if (t == SCAN_BLK - 1) g_bsums[blockIdx.x] = sh[t];
}
__global__ void k_scan2() {
    __shared__ int sh[1024];
    int t = threadIdx.x;
    int v = (t < NB_SCAN) ? g_bsums[t] : 0;
    sh[t] = v;
    __syncthreads();
    for (int off = 1; off < 1024; off <<= 1) {
        int add = (t >= off) ? sh[t - off] : 0;
        __syncthreads();
        sh[t] += add;
        __syncthreads();
    }
    if (t < NB_SCAN) g_boffs[t] = sh[t] - v;
    if (t == 1023)   g_rowptr[NTOT] = sh[1023];
}
__global__ void k_scan3() {
    int i = blockIdx.x * blockDim.x + threadIdx.x;
    if (i < NTOT) {
        int r = g_rowptr[i] + g_boffs[i >> 8];
        g_rowptr[i] = r;
        g_cursor[i] = r;
    }
}
__global__ void k_scatter(const int* __restrict__ rows,
                          const int* __restrict__ cols,
                          const float* __restrict__ vals) {
    int e = blockIdx.x * blockDim.x + threadIdx.x;
    if (e < NNZ) {
        int p = atomicAdd(&g_cursor[rows[e]], 1);
        g_edges[p] = make_int2(cols[e], __float_as_int(vals[e]));
    }
}

// ---------------- helpers ----------------
__device__ __forceinline__ void h16_to_f8(uint4 r, float* f) {
    float2 t;
    t = __half22float2(*(__half2*)&r.x); f[0] = t.x; f[1] = t.y;
    t = __half22float2(*(__half2*)&r.y); f[2] = t.x; f[3] = t.y;
    t = __half22float2(*(__half2*)&r.z); f[4] = t.x; f[5] = t.y;
    t = __half22float2(*(__half2*)&r.w); f[6] = t.x; f[7] = t.y;
}
// 8 signed int8 (uint2) -> 8 floats (unscaled)
__device__ __forceinline__ void q8_to_f8(uint2 r, float* f) {
    int a = (int)r.x, b = (int)r.y;
    f[0] = (float)((a << 24) >> 24);
    f[1] = (float)((a << 16) >> 24);
    f[2] = (float)((a <<  8) >> 24);
    f[3] = (float)( a        >> 24);
    f[4] = (float)((b << 24) >> 24);
    f[5] = (float)((b << 16) >> 24);
    f[6] = (float)((b <<  8) >> 24);
    f[7] = (float)( b        >> 24);
}
// 8 floats -> 8 int8 packed (caller guarantees |f[k]*inv| <= 127)
__device__ __forceinline__ uint2 f8_to_q8(const float* f, float inv) {
    int q0 = __float2int_rn(f[0] * inv) & 0xFF;
    int q1 = __float2int_rn(f[1] * inv) & 0xFF;
    int q2 = __float2int_rn(f[2] * inv) & 0xFF;
    int q3 = __float2int_rn(f[3] * inv) & 0xFF;
    int q4 = __float2int_rn(f[4] * inv) & 0xFF;
    int q5 = __float2int_rn(f[5] * inv) & 0xFF;
    int q6 = __float2int_rn(f[6] * inv) & 0xFF;
    int q7 = __float2int_rn(f[7] * inv) & 0xFF;
    uint2 r;
    r.x = (unsigned)(q0 | (q1 << 8) | (q2 << 16) | (q3 << 24));
    r.y = (unsigned)(q4 | (q5 << 8) | (q6 << 16) | (q7 << 24));
    return r;
}

// ---------------- fused propagate layer (4 rows per warp) ----------------
// MODE 0: gather fp16 hEgo (128B rows); compute ||ego||; write int8 x1.
// MODE 1: gather int8 + per-row scale (64B rows + bcast scale); write int8 xn.
// MODE 2: gather int8; out = ego + deq(x1)+deq(x2)+deq(x3) + r (fused epilogue).
template<int MODE>
__global__ __launch_bounds__(256) void k_prop(const uint4* __restrict__ xh,
                                              const uint2* __restrict__ xq,
                                              const float* __restrict__ xs,
                                              uint2* __restrict__ qo,
                                              float* __restrict__ so,
                                              float4* __restrict__ out)
{
    const unsigned FULL = 0xffffffffu;
    int warp = (blockIdx.x * blockDim.x + threadIdx.x) >> 5;
    int lane = threadIdx.x & 31;
    int hl   = lane & 7;
    int row  = warp * 4 + (lane >> 3);
    if (row >= NTOT) return;

    int beg = g_rowptr[row];
    int end = g_rowptr[row + 1];

    float acc[8];
    #pragma unroll
    for (int k = 0; k < 8; ++k) acc[k] = 0.f;

    int e = beg;
    for (; e + 4 <= end; e += 4) {
        int2 e0 = g_edges[e+0];
        int2 e1 = g_edges[e+1];
        int2 e2 = g_edges[e+2];
        int2 e3 = g_edges[e+3];
        float x0[8], x1[8], x2[8], x3[8];
        float v0, v1, v2, v3;
        if (MODE == 0) {
            uint4 r0 = xh[e0.x * 8 + hl];
            uint4 r1 = xh[e1.x * 8 + hl];
            uint4 r2 = xh[e2.x * 8 + hl];
            uint4 r3 = xh[e3.x * 8 + hl];
            h16_to_f8(r0, x0);
            h16_to_f8(r1, x1);
            h16_to_f8(r2, x2);
            h16_to_f8(r3, x3);
            v0 = __int_as_float(e0.y);
            v1 = __int_as_float(e1.y);
            v2 = __int_as_float(e2.y);
            v3 = __int_as_float(e3.y);
        } else {
            uint2 r0 = xq[e0.x * 8 + hl];
            uint2 r1 = xq[e1.x * 8 + hl];
            uint2 r2 = xq[e2.x * 8 + hl];
            uint2 r3 = xq[e3.x * 8 + hl];
            float s0 = xs[e0.x];
            float s1 = xs[e1.x];
            float s2 = xs[e2.x];
            float s3 = xs[e3.x];
            q8_to_f8(r0, x0);
            q8_to_f8(r1, x1);
            q8_to_f8(r2, x2);
            q8_to_f8(r3, x3);
            v0 = __int_as_float(e0.y) * s0;
            v1 = __int_as_float(e1.y) * s1;
            v2 = __int_as_float(e2.y) * s2;
            v3 = __int_as_float(e3.y) * s3;
        }
        #pragma unroll
        for (int k = 0; k < 8; ++k)
            acc[k] += v0*x0[k] + v1*x1[k] + v2*x2[k] + v3*x3[k];
    }
    for (; e < end; ++e) {
        int2  cv = g_edges[e];
        float xv[8];
        float v;
        if (MODE == 0) {
            h16_to_f8(xh[cv.x * 8 + hl], xv);
            v = __int_as_float(cv.y);
        } else {
            q8_to_f8(xq[cv.x * 8 + hl], xv);
            v = __int_as_float(cv.y) * xs[cv.x];
        }
        #pragma unroll
        for (int k = 0; k < 8; ++k) acc[k] += v * xv[k];
    }

    const float4* egof = (const float4*)g_ego;
    float4 ea = egof[row * 16 + hl * 2];
    float4 eb = egof[row * 16 + hl * 2 + 1];
    float eg[8] = {ea.x, ea.y, ea.z, ea.w, eb.x, eb.y, eb.z, eb.w};

    float dot = 0.f, nrm = 0.f, egn = 0.f;
    #pragma unroll
    for (int k = 0; k < 8; ++k) {
        dot += acc[k] * eg[k];
        nrm += acc[k] * acc[k];
        if (MODE == 0) egn += eg[k] * eg[k];
    }
    #pragma unroll
    for (int o = 4; o; o >>= 1) {
        dot += __shfl_xor_sync(FULL, dot, o);
        nrm += __shfl_xor_sync(FULL, nrm, o);
        if (MODE == 0) egn += __shfl_xor_sync(FULL, egn, o);
    }

    float ego_norm;
    if (MODE == 0) {
        ego_norm = sqrtf(egn);
        if (hl == 0) g_norm[row] = ego_norm;
    } else {
        ego_norm = g_norm[row];
    }
    float w = dot / fmaxf(sqrtf(nrm) * ego_norm, EPS_);

    float r[8];
    #pragma unroll
    for (int k = 0; k < 8; ++k) r[k] = w * acc[k];

    if (MODE == 2) {
        float s1v = g_s1[row], s2v = g_s2[row], s3v = g_s3[row];
        float a1[8], a2[8], a3[8];
        q8_to_f8(g_q1[row * 8 + hl], a1);
        q8_to_f8(g_q2[row * 8 + hl], a2);
        q8_to_f8(g_q3[row * 8 + hl], a3);
        float o0[8];
        #pragma unroll
        for (int k = 0; k < 8; ++k)
            o0[k] = eg[k] + s1v*a1[k] + s2v*a2[k] + s3v*a3[k] + r[k];
        out[row * 16 + hl * 2]     = make_float4(o0[0], o0[1], o0[2], o0[3]);
        out[row * 16 + hl * 2 + 1] = make_float4(o0[4], o0[5], o0[6], o0[7]);
    } else {
        // quantize row of r to int8 with per-row max scale
        float m = 0.f;
        #pragma unroll
        for (int k = 0; k < 8; ++k) m = fmaxf(m, fabsf(r[k]));
        #pragma unroll
        for (int o = 4; o; o >>= 1)
            m = fmaxf(m, __shfl_xor_sync(FULL, m, o));
        float scale = m * (1.f / 127.f);
        float inv   = (m > 0.f) ? (127.f / m) : 0.f;
        qo[row * 8 + hl] = f8_to_q8(r, inv);
        if (hl == 0) so[row] = scale;
    }
}

// ---------------- launch ----------------
extern "C" void kernel_launch(void* const* d_in, const int* in_sizes, int n_in,
                              void* d_out, int out_size)
{
    const float* user_fea = (const float*)d_in[0];
    const float* item_fea = (const float*)d_in[1];
    const float* prompt   = (const float*)d_in[2];
    const float* mlp_w    = (const float*)d_in[3];
    const float* mlp_b    = (const float*)d_in[4];
    const int*   adj_rows = (const int*)  d_in[5];
    const int*   adj_cols = (const int*)  d_in[6];
    const float* adj_vals = (const float*)d_in[7];
    float* out = (float*)d_out;

    static cudaStream_t s2 = nullptr;
    static cudaEvent_t  evFork = nullptr, evJoin = nullptr;
    if (s2 == nullptr) {
        cudaStreamCreateWithFlags(&s2, cudaStreamNonBlocking);
        cudaEventCreateWithFlags(&evFork, cudaEventDisableTiming);
        cudaEventCreateWithFlags(&evJoin, cudaEventDisableTiming);
    }

    void* degp = nullptr;
    uint4* hEgo = nullptr;
    uint2 *q1 = nullptr, *q2 = nullptr, *q3 = nullptr;
    float *s1 = nullptr, *s2p = nullptr, *s3 = nullptr;
    cudaGetSymbolAddress(&degp, g_deg);
    cudaGetSymbolAddress((void**)&hEgo, g_hEgo);
    cudaGetSymbolAddress((void**)&q1, g_q1);
    cudaGetSymbolAddress((void**)&q2, g_q2);
    cudaGetSymbolAddress((void**)&q3, g_q3);
    cudaGetSymbolAddress((void**)&s1, g_s1);
    cudaGetSymbolAddress((void**)&s2p, g_s2);
    cudaGetSymbolAddress((void**)&s3, g_s3);
    float4* out4 = (float4*)out;

    // ---- fork: CSR build on s2, embeddings on capture (default) stream ----
    cudaEventRecord(evFork, 0);
    cudaStreamWaitEvent(s2, evFork, 0);

    // branch A (default stream): embeddings
    k_user_ego<<<(N_USER * EMB + 255) / 256, 256>>>(user_fea, prompt);
    k_gemm    <<<(N_ITEM + 63) / 64, 256>>>(item_fea, mlp_w, mlp_b);

    // branch B (s2): CSR build
    cudaMemsetAsync(degp, 0, NTOT * sizeof(int), s2);
    k_hist    <<<(NNZ + 255) / 256, 256, 0, s2>>>(adj_rows);
    k_scan1   <<<NB_SCAN, SCAN_BLK, 0, s2>>>();
    k_scan2   <<<1, 1024, 0, s2>>>();
    k_scan3   <<<(NTOT + 255) / 256, 256, 0, s2>>>();
    k_scatter <<<(NNZ + 255) / 256, 256, 0, s2>>>(adj_rows, adj_cols, adj_vals);

    // ---- join ----
    cudaEventRecord(evJoin, s2);
    cudaStreamWaitEvent(0, evJoin, 0);

    // --- 4 propagation layers; last layer fuses the output epilogue ---
    int nwarp   = (NTOT + 3) / 4;                      // 4 rows per warp
    int pblocks = (nwarp * 32 + 255) / 256;
    k_prop<0><<<pblocks, 256>>>(hEgo, nullptr, nullptr, q1, s1,  nullptr);
    k_prop<1><<<pblocks, 256>>>(nullptr, q1, s1,        q2, s2p, nullptr);
    k_prop<1><<<pblocks, 256>>>(nullptr, q2, s2p,       q3, s3,  nullptr);
    k_prop<2><<<pblocks, 256>>>(nullptr, q3, s3,  nullptr, nullptr, out4);
}